// round 11
// baseline (speedup 1.0000x reference)
#include <cuda_runtime.h>

#define NQ 9
#define KK 3
#define S 16
#define H 128
#define B 16
#define D 512
#define NTH 512

// scratch (static __device__ — no allocation)
__device__ float2 g_rhoq[S * B * NQ * 4];     // [t][b][n][r*2+c]
__device__ float2 g_A[B * S * 256];           // kron of qubits 0..3 (16x16)
__device__ float2 g_Bm[B * S * 1024];         // kron of qubits 4..8 (32x32)

__device__ __forceinline__ float2 cmul(float2 a, float2 b) {
    return make_float2(a.x * b.x - a.y * b.y, a.x * b.y + a.y * b.x);
}
__device__ __forceinline__ float sigmoidf_(float x) { return 1.0f / (1.0f + expf(-x)); }

// packed f32x2 FMA (SASS FFMA2; PTX-only per sm_103a)
__device__ __forceinline__ void fma2(unsigned long long &acc,
                                     unsigned long long a, unsigned long long b) {
    asm("fma.rn.f32x2 %0, %1, %2, %3;" : "=l"(acc) : "l"(a), "l"(b), "l"(acc));
}
__device__ __forceinline__ float2 unpack2(unsigned long long v) {
    float lo, hi;
    asm("mov.b64 {%0, %1}, %2;" : "=f"(lo), "=f"(hi) : "l"(v));
    return make_float2(lo, hi);
}

// ---- dynamic smem layout (float offsets) ----
// Whh: ALL 512 rows, chunks 0..23 (16B chunks), swizzled: 512*24*4 = 49152 floats
#define F_WHH   0
#define F_WP    49152               // 27*132 = 3564
#define F_PSI0  52716               // 512 float2 = 1024
#define F_EXCH  53740               // 2*512 float2 = 2048
#define F_G     55788               // 512
#define F_BSUM  56300               // 512
#define F_H     56812               // 128
#define F_C     56940               // 128
#define F_X     57068               // 40
#define F_AMPS  57108               // 28
#define F_LOG   57136               // 28
#define F_RED   57164               // 192
#define F_NORM  57356               // 12
#define F_NN0   57368               // 4 (pad)
#define SMEM_FLOATS 57372           // = 229,488 bytes (< 232,448 opt-in limit)

// ---------------------------------------------------------------------------
// Kernel 1: sequential LSTM + measurement chain. One block per batch,
// 512 threads. psi in registers. Gate GEMM: chunk-split Whh (24 smem chunks +
// 8 global chunks per row, uniform across ALL warps — no straggler warps),
// phase-ordered so the smem FMAs hide the L2 latency of the global loads.
// ---------------------------------------------------------------------------
__global__ void __launch_bounds__(NTH, 1) k_seq(
    const float* __restrict__ snapshot, const float* __restrict__ bcv,
    const float* __restrict__ rho, const float* __restrict__ h0,
    const float* __restrict__ c0, const float* __restrict__ Wih,
    const float* __restrict__ Whh, const float* __restrict__ bih,
    const float* __restrict__ bhh, const float* __restrict__ Wp,
    const float* __restrict__ bp, float* __restrict__ bv_out)
{
    extern __shared__ float sm[];
    const int b = blockIdx.x;
    const int tid = threadIdx.x;
    const int lane = tid & 31;
    const int wid = tid >> 5;

    float2* s_psi0 = (float2*)(sm + F_PSI0);
    float2* s_exch = (float2*)(sm + F_EXCH);
    float*  s_g    = sm + F_G;
    float*  s_bsum = sm + F_BSUM;
    float*  s_h    = sm + F_H;
    float*  s_c    = sm + F_C;
    float*  s_x    = sm + F_X;
    float*  s_amps = sm + F_AMPS;
    float*  s_log  = sm + F_LOG;
    float*  s_red  = sm + F_RED;
    float*  s_norm = sm + F_NORM;

    // ---- one-time loads ----
    // Whh chunks 0..23 of EVERY row into smem.
    // Row stride = 24 chunks (384B). Swizzle low-3 chunk bits with row&7 so a
    // quarter-warp's 8 LDS.128 hit 8 distinct bank groups.
    {
        float4* dst = (float4*)(sm + F_WHH);
        const float4* src = (const float4*)Whh;
        for (int i = tid; i < 512 * 24; i += NTH) {
            int row = i / 24, c = i % 24;
            dst[row * 24 + ((c & 24) | ((c & 7) ^ (row & 7)))] =
                __ldg(src + row * 32 + c);
        }
    }
    // Wp into smem, row pad to 132 floats (33 chunks)
    {
        float4* dst = (float4*)(sm + F_WP);
        const float4* src = (const float4*)Wp;
        for (int i = tid; i < 27 * 32; i += NTH) {
            int row = i >> 5, c4 = i & 31;
            dst[row * 33 + c4] = __ldg(src + i);
        }
    }
    s_bsum[tid] = __ldg(bih + tid) + __ldg(bhh + tid);
    s_psi0[tid] = make_float2(rho[b * 1024 + tid], rho[b * 1024 + 512 + tid]);
    if (tid < 128) { s_h[tid] = h0[b * H + tid]; s_c[tid] = c0[b * H + tid]; }
    if (tid < 9)  s_x[tid] = snapshot[b * NQ + tid];
    if (tid >= 9 && tid < 36) s_x[tid] = bcv[b * 27 + tid - 9];
    __syncthreads();

    // nn0 = ||psi0||^2  (psi0 is NOT normalized in the reference)
    {
        float2 v = s_psi0[tid];
        float nn = v.x * v.x + v.y * v.y;
        #pragma unroll
        for (int off = 16; off; off >>= 1) nn += __shfl_xor_sync(0xffffffffu, nn, off);
        if (lane == 0) s_red[wid * 12] = nn;
        __syncthreads();
        if (tid == 0) {
            float s = 0.0f;
            #pragma unroll
            for (int w = 0; w < 16; w++) s += s_red[w * 12];
            sm[F_NN0] = s;
        }
        __syncthreads();
    }

    for (int t = 0; t < S; t++) {
        // ---- emit rho_q for the current input x ----
        if (tid < 9) {
            int n = tid;
            float sh = s_x[n];
            float p0 = s_x[9 + n * 3 + 0];
            float p1 = s_x[9 + n * 3 + 1];
            float p2 = s_x[9 + n * 3 + 2];
            float2* m = &g_rhoq[(t * B + b) * NQ * 4 + n * 4];
            m[0] = make_float2(0.5f * (1.0f + 3.0f * sh * p2), 0.0f);
            m[1] = make_float2(1.5f * sh * p0, -1.5f * sh * p1);
            m[2] = make_float2(1.5f * sh * p0,  1.5f * sh * p1);
            m[3] = make_float2(0.5f * (1.0f - 3.0f * sh * p2), 0.0f);
        }
        if (t == S - 1) break;

        // ---- LSTM gates: one row per thread, phase-ordered loads ----
        {
            const int r = tid;
            // phase 1: issue ALL independent global loads up front (MLP)
            const ulonglong2* wi = (const ulonglong2*)(Wih + r * 36);
            ulonglong2 wi_reg[9];
            #pragma unroll
            for (int k = 0; k < 9; k++) wi_reg[k] = __ldg(wi + k);
            const ulonglong2* wt = (const ulonglong2*)(Whh + r * 128 + 96);
            ulonglong2 wt_reg[8];
            #pragma unroll
            for (int k = 0; k < 8; k++) wt_reg[k] = __ldg(wt + k);

            unsigned long long a01 = 0ull, a23 = 0ull, b01 = 0ull, b23 = 0ull;
            // phase 2: smem Whh chunks 0..23 — hides L2 latency of phase 1
            const ulonglong2* wrow = (const ulonglong2*)(sm + F_WHH) + r * 24;
            const ulonglong2* h2 = (const ulonglong2*)s_h;
            const int sw = r & 7;
            #pragma unroll
            for (int k = 0; k < 24; k++) {
                ulonglong2 w = wrow[(k & 24) | ((k & 7) ^ sw)];
                ulonglong2 hv = h2[k];
                if (k & 1) { fma2(b01, w.x, hv.x); fma2(b23, w.y, hv.y); }
                else       { fma2(a01, w.x, hv.x); fma2(a23, w.y, hv.y); }
            }
            // phase 3: consume landed global registers
            #pragma unroll
            for (int k = 0; k < 8; k++) {
                ulonglong2 hv = h2[24 + k];
                if (k & 1) { fma2(b01, wt_reg[k].x, hv.x); fma2(b23, wt_reg[k].y, hv.y); }
                else       { fma2(a01, wt_reg[k].x, hv.x); fma2(a23, wt_reg[k].y, hv.y); }
            }
            const ulonglong2* x2 = (const ulonglong2*)s_x;
            #pragma unroll
            for (int k = 0; k < 9; k++) {
                ulonglong2 xv = x2[k];
                if (k & 1) { fma2(b01, wi_reg[k].x, xv.x); fma2(b23, wi_reg[k].y, xv.y); }
                else       { fma2(a01, wi_reg[k].x, xv.x); fma2(a23, wi_reg[k].y, xv.y); }
            }
            float2 fa = unpack2(a01), fb = unpack2(a23);
            float2 fc = unpack2(b01), fd = unpack2(b23);
            s_g[r] = ((fa.x + fa.y) + (fb.x + fb.y))
                   + ((fc.x + fc.y) + (fd.x + fd.y)) + s_bsum[r];
        }
        __syncthreads();

        // ---- elementwise LSTM update ----
        if (tid < 128) {
            float ig = sigmoidf_(s_g[tid]);
            float fg = sigmoidf_(s_g[128 + tid]);
            float gg = tanhf(s_g[256 + tid]);
            float og = sigmoidf_(s_g[384 + tid]);
            float c = fg * s_c[tid] + ig * gg;
            s_c[tid] = c;
            s_h[tid] = og * tanhf(c);
        }
        __syncthreads();

        // ---- projector logits: 27 outputs x 16 threads ----
        // ALL threads execute the shuffles (clamped index) to keep full-warp
        // participation in __shfl_down_sync.
        {
            int grp = tid >> 4, l = tid & 15;
            int grpc = grp < 27 ? grp : 26;
            const float4* wr = (const float4*)(sm + F_WP + grpc * 132) + l * 2;
            const float4* h4 = (const float4*)s_h + l * 2;
            float4 w0 = wr[0], w1 = wr[1];
            float4 v0 = h4[0], v1 = h4[1];
            float p = w0.x * v0.x + w0.y * v0.y + w0.z * v0.z + w0.w * v0.w
                    + w1.x * v1.x + w1.y * v1.y + w1.z * v1.z + w1.w * v1.w;
            p += __shfl_down_sync(0xffffffffu, p, 8, 16);
            p += __shfl_down_sync(0xffffffffu, p, 4, 16);
            p += __shfl_down_sync(0xffffffffu, p, 2, 16);
            p += __shfl_down_sync(0xffffffffu, p, 1, 16);
            if (l == 0 && grp < 27) s_log[grp] = p + __ldg(bp + grp);
        }
        __syncthreads();
        if (tid < 9) {
            float l0 = s_log[tid * 3], l1 = s_log[tid * 3 + 1], l2 = s_log[tid * 3 + 2];
            float m = fmaxf(l0, fmaxf(l1, l2));
            float e0 = expf(l0 - m), e1 = expf(l1 - m), e2 = expf(l2 - m);
            float inv = 1.0f / (e0 + e1 + e2);
            s_amps[tid * 3 + 0] = sqrtf(e0 * inv);
            s_amps[tid * 3 + 1] = sqrtf(e1 * inv);
            s_amps[tid * 3 + 2] = sqrtf(e2 * inv);
        }
        __syncthreads();

        // ---- 9 collapses, psi in registers, unnormalized with deferred norms ----
        {
            float2 v = s_psi0[tid];
            float nrm[9];
            #pragma unroll
            for (int q = 0; q < 9; q++) {
                float a1 = s_amps[q * 3], a2 = s_amps[q * 3 + 1], a3 = s_amps[q * 3 + 2];
                float an  = sqrtf(a1 * a1 + a2 * a2 + a3 * a3);
                float apn = a3 + an;
                float inv2 = 1.0f / (2.0f * an * apn);
                float t00 = apn * apn * inv2;
                float t11 = (a1 * a1 + a2 * a2) * inv2;
                float cr  = apn * a1 * inv2;
                float ci  = apn * a2 * inv2;
                const int p = 8 - q;
                const int d = 1 << p;
                float2 w;
                if (p >= 5) {
                    float2* buf = s_exch + (q & 1) * 512;
                    buf[tid] = v;
                    __syncthreads();
                    w = buf[tid ^ d];
                } else {
                    w.x = __shfl_xor_sync(0xffffffffu, v.x, d);
                    w.y = __shfl_xor_sync(0xffffffffu, v.y, d);
                }
                bool hi = (tid & d) != 0;
                float td = hi ? t11 : t00;
                float sg = hi ? -ci : ci;
                float2 nv;
                nv.x = td * v.x + cr * w.x + sg * w.y;
                nv.y = td * v.y + cr * w.y - sg * w.x;
                v = nv;
                nrm[q] = v.x * v.x + v.y * v.y;
            }
            // batched reduction of 9 norms
            #pragma unroll
            for (int q = 0; q < 9; q++) {
                float val = nrm[q];
                #pragma unroll
                for (int off = 16; off; off >>= 1)
                    val += __shfl_xor_sync(0xffffffffu, val, off);
                if (lane == 0) s_red[wid * 12 + q] = val;
            }
            __syncthreads();
            if (tid < 9) {
                float ssum = 0.0f;
                #pragma unroll
                for (int w = 0; w < 16; w++) ssum += s_red[w * 12 + tid];
                s_norm[tid] = ssum;
            }
            __syncthreads();
        }

        // ---- build next input x = [snap(9), amps(27)] ----
        // psi0 is UNNORMALIZED: s_0 = 2*||P0 psi0||^2 - ||psi0||^2.
        // For q >= 1 the chain is normalized: s_q = 2*nrm[q]/nrm[q-1] - 1.
        if (tid < 9) {
            float sq;
            if (tid == 0) sq = 2.0f * s_norm[0] - sm[F_NN0];
            else          sq = 2.0f * s_norm[tid] / s_norm[tid - 1] - 1.0f;
            s_x[tid] = sq;
        } else if (tid < 36) {
            s_x[tid] = s_amps[tid - 9];
        }
        if (t == S - 2 && bv_out != nullptr && tid < 27)
            bv_out[b * 27 + tid] = s_amps[tid];
        __syncthreads();
    }
}

// ---------------------------------------------------------------------------
// Kernel 2: partial Kronecker products per (b, t)
// ---------------------------------------------------------------------------
__global__ void __launch_bounds__(256) k_kron()
{
    int bi = blockIdx.x;            // 0 .. S*B-1
    int b = bi >> 4;
    int t = bi & 15;
    __shared__ float2 s_m[NQ * 4];
    int tid = threadIdx.x;
    if (tid < NQ * 4) s_m[tid] = g_rhoq[(t * B + b) * NQ * 4 + tid];
    __syncthreads();

    // A: qubits 0..3 -> 16x16
    {
        int r = tid >> 4, c = tid & 15;
        float2 v = s_m[0 * 4 + ((r >> 3) & 1) * 2 + ((c >> 3) & 1)];
        #pragma unroll
        for (int q = 1; q < 4; q++) {
            float2 m = s_m[q * 4 + ((r >> (3 - q)) & 1) * 2 + ((c >> (3 - q)) & 1)];
            v = cmul(v, m);
        }
        g_A[(b * S + t) * 256 + tid] = v;
    }
    // B: qubits 4..8 -> 32x32 (4 elems per thread)
    #pragma unroll
    for (int j = 0; j < 4; j++) {
        int lp = tid + j * 256;
        int r = lp >> 5, c = lp & 31;
        float2 v = s_m[4 * 4 + ((r >> 4) & 1) * 2 + ((c >> 4) & 1)];
        #pragma unroll
        for (int q = 5; q < 9; q++) {
            float2 m = s_m[q * 4 + ((r >> (8 - q)) & 1) * 2 + ((c >> (8 - q)) & 1)];
            v = cmul(v, m);
        }
        g_Bm[(b * S + t) * 1024 + lp] = v;
    }
}

// ---------------------------------------------------------------------------
// Kernel 3: acc[b][hp][lp] = (1/S) * sum_t A_t[hp] * B_t[lp], scatter to out
// out layout: [B][2][512][512]  (real plane, imag plane)
// ---------------------------------------------------------------------------
__global__ void __launch_bounds__(256) k_acc(float* __restrict__ out)
{
    int b = blockIdx.z;
    int hpBase = blockIdx.x * 16;
    int tx = threadIdx.x;                 // 0..31 -> lo_c
    int ty = threadIdx.y;                 // 0..7
    int lo_r = blockIdx.y * 8 + ty;
    int lp = lo_r * 32 + tx;
    __shared__ float2 A_s[S][16];
    int tid = ty * 32 + tx;
    {
        int t = tid >> 4, j = tid & 15;
        A_s[t][j] = g_A[(b * S + t) * 256 + hpBase + j];
    }
    __syncthreads();

    float2 acc[16];
    #pragma unroll
    for (int j = 0; j < 16; j++) acc[j] = make_float2(0.0f, 0.0f);

    #pragma unroll
    for (int t = 0; t < S; t++) {
        float2 bv = g_Bm[(b * S + t) * 1024 + lp];
        #pragma unroll
        for (int j = 0; j < 16; j++) {
            float2 a = A_s[t][j];
            acc[j].x += a.x * bv.x - a.y * bv.y;
            acc[j].y += a.x * bv.y + a.y * bv.x;
        }
    }

    const float sc = 1.0f / (float)S;
    float* outr = out + (size_t)b * 2 * D * D;
    float* outi = outr + D * D;
    #pragma unroll
    for (int j = 0; j < 16; j++) {
        int hp = hpBase + j;
        int row = (hp >> 4) * 32 + lo_r;
        int col = (hp & 15) * 32 + tx;
        outr[row * D + col] = acc[j].x * sc;
        outi[row * D + col] = acc[j].y * sc;
    }
}

// ---------------------------------------------------------------------------
extern "C" void kernel_launch(void* const* d_in, const int* in_sizes, int n_in,
                              void* d_out, int out_size)
{
    const float* snapshot = (const float*)d_in[0];
    const float* bcv      = (const float*)d_in[1];
    const float* rho      = (const float*)d_in[2];
    const float* h0       = (const float*)d_in[3];
    const float* c0       = (const float*)d_in[4];
    const float* Wih      = (const float*)d_in[5];
    const float* Whh      = (const float*)d_in[6];
    const float* bih      = (const float*)d_in[7];
    const float* bhh      = (const float*)d_in[8];
    const float* Wp       = (const float*)d_in[9];
    const float* bp       = (const float*)d_in[10];

    float* out = (float*)d_out;
    const int main_elems = 2 * B * D * D;
    const int bv_elems = B * NQ * KK;
    float* bv_out = (out_size >= main_elems + bv_elems) ? (out + main_elems) : nullptr;

    // Unconditional (no static guards). Host API, enqueues nothing — capture-safe.
    cudaFuncSetAttribute(k_seq, cudaFuncAttributeMaxDynamicSharedMemorySize,
                         SMEM_FLOATS * (int)sizeof(float));

    k_seq<<<B, NTH, SMEM_FLOATS * sizeof(float)>>>(
        snapshot, bcv, rho, h0, c0, Wih, Whh, bih, bhh, Wp, bp, bv_out);
    k_kron<<<S * B, 256>>>();
    dim3 g3(16, 4, B);
    k_acc<<<g3, dim3(32, 8)>>>(out);
}

// round 12
// speedup vs baseline: 1.8785x; 1.8785x over previous
#include <cuda_runtime.h>

#define NQ 9
#define KK 3
#define S 16
#define H 128
#define B 16
#define D 512
#define NTH 512

// scratch (static __device__ — no allocation)
__device__ float2 g_rhoq[S * B * NQ * 4];     // [t][b][n][r*2+c]
__device__ float2 g_A[B * S * 256];           // kron of qubits 0..3 (16x16)
__device__ float2 g_Bm[B * S * 1024];         // kron of qubits 4..8 (32x32)
// transposed weights: [chunk][row] so thread=row loads are coalesced
__device__ ulonglong2 g_WhhT[32 * 512];       // Whh row r, 16B chunk k4 -> [k4*512 + r]
__device__ ulonglong2 g_WihT[9 * 512];        // Wih row r, 16B chunk k  -> [k*512 + r]

__device__ __forceinline__ float2 cmul(float2 a, float2 b) {
    return make_float2(a.x * b.x - a.y * b.y, a.x * b.y + a.y * b.x);
}
__device__ __forceinline__ float sigmoidf_(float x) { return 1.0f / (1.0f + expf(-x)); }

// packed f32x2 FMA (SASS FFMA2; PTX-only per sm_103a)
__device__ __forceinline__ void fma2(unsigned long long &acc,
                                     unsigned long long a, unsigned long long b) {
    asm("fma.rn.f32x2 %0, %1, %2, %3;" : "=l"(acc) : "l"(a), "l"(b), "l"(acc));
}
__device__ __forceinline__ float2 unpack2(unsigned long long v) {
    float lo, hi;
    asm("mov.b64 {%0, %1}, %2;" : "=f"(lo), "=f"(hi) : "l"(v));
    return make_float2(lo, hi);
}

// ---------------------------------------------------------------------------
// Kernel 0: transpose weights into [chunk][row] layout (coalesced writes).
// 20992 16B-chunks total -> 82 blocks x 256 threads.
// ---------------------------------------------------------------------------
__global__ void __launch_bounds__(256) k_transpose(
    const float* __restrict__ Whh, const float* __restrict__ Wih)
{
    int idx = blockIdx.x * 256 + threadIdx.x;
    if (idx < 32 * 512) {
        int k4 = idx >> 9, r = idx & 511;
        g_WhhT[idx] = __ldg((const ulonglong2*)Whh + r * 32 + k4);
    }
    int j = idx - 32 * 512;
    if (j >= 0 && j < 9 * 512) {
        int k = j >> 9, r = j & 511;
        g_WihT[j] = __ldg((const ulonglong2*)Wih + r * 9 + k);
    }
}

// ---------------------------------------------------------------------------
// Kernel 1: sequential LSTM + measurement chain. One block per batch,
// 512 threads. psi in registers. Gate GEMM: one row per thread, ALL weight
// loads coalesced via transposed layout (4 L1TEX wavefronts per warp-LDG.128
// instead of 32 with row-major). Static smem only (~33KB).
// ---------------------------------------------------------------------------
__global__ void __launch_bounds__(NTH, 1) k_seq(
    const float* __restrict__ snapshot, const float* __restrict__ bcv,
    const float* __restrict__ rho, const float* __restrict__ h0,
    const float* __restrict__ c0, const float* __restrict__ bih,
    const float* __restrict__ bhh, const float* __restrict__ Wp,
    const float* __restrict__ bp, float* __restrict__ bv_out)
{
    const int b = blockIdx.x;
    const int tid = threadIdx.x;
    const int lane = tid & 31;
    const int wid = tid >> 5;

    __shared__ float2 s_psi0[512];
    __shared__ float2 s_exch[2][512];
    __shared__ float s_g[512];
    __shared__ float s_bsum[512];
    __shared__ __align__(16) float s_h[128];
    __shared__ float s_c[128];
    __shared__ __align__(16) float s_x[36];
    __shared__ float s_amps[27];
    __shared__ float s_log[27];
    __shared__ float s_red[16 * 12];
    __shared__ float s_norm[9];
    __shared__ float s_nn0;
    __shared__ __align__(16) float s_wp[27 * 132];

    // ---- one-time loads ----
    // Wp into smem, row pad to 132 floats (33 chunks)
    {
        float4* dst = (float4*)s_wp;
        const float4* src = (const float4*)Wp;
        for (int i = tid; i < 27 * 32; i += NTH) {
            int row = i >> 5, c4 = i & 31;
            dst[row * 33 + c4] = __ldg(src + i);
        }
    }
    s_bsum[tid] = __ldg(bih + tid) + __ldg(bhh + tid);
    s_psi0[tid] = make_float2(rho[b * 1024 + tid], rho[b * 1024 + 512 + tid]);
    if (tid < 128) { s_h[tid] = h0[b * H + tid]; s_c[tid] = c0[b * H + tid]; }
    if (tid < 9)  s_x[tid] = snapshot[b * NQ + tid];
    if (tid >= 9 && tid < 36) s_x[tid] = bcv[b * 27 + tid - 9];
    __syncthreads();

    // nn0 = ||psi0||^2  (psi0 is NOT normalized in the reference)
    {
        float2 v = s_psi0[tid];
        float nn = v.x * v.x + v.y * v.y;
        #pragma unroll
        for (int off = 16; off; off >>= 1) nn += __shfl_xor_sync(0xffffffffu, nn, off);
        if (lane == 0) s_red[wid * 12] = nn;
        __syncthreads();
        if (tid == 0) {
            float s = 0.0f;
            #pragma unroll
            for (int w = 0; w < 16; w++) s += s_red[w * 12];
            s_nn0 = s;
        }
        __syncthreads();
    }

    for (int t = 0; t < S; t++) {
        // ---- emit rho_q for the current input x ----
        if (tid < 9) {
            int n = tid;
            float sh = s_x[n];
            float p0 = s_x[9 + n * 3 + 0];
            float p1 = s_x[9 + n * 3 + 1];
            float p2 = s_x[9 + n * 3 + 2];
            float2* m = &g_rhoq[(t * B + b) * NQ * 4 + n * 4];
            m[0] = make_float2(0.5f * (1.0f + 3.0f * sh * p2), 0.0f);
            m[1] = make_float2(1.5f * sh * p0, -1.5f * sh * p1);
            m[2] = make_float2(1.5f * sh * p0,  1.5f * sh * p1);
            m[3] = make_float2(0.5f * (1.0f - 3.0f * sh * p2), 0.0f);
        }
        if (t == S - 1) break;

        // ---- LSTM gates: one row per thread, coalesced transposed loads ----
        {
            const int r = tid;
            unsigned long long a01 = 0ull, a23 = 0ull, b01 = 0ull, b23 = 0ull;
            const ulonglong2* h2 = (const ulonglong2*)s_h;
            #pragma unroll
            for (int k = 0; k < 32; k++) {
                ulonglong2 w = __ldg(g_WhhT + (k << 9) + r);   // coalesced
                ulonglong2 hv = h2[k];                          // broadcast
                if (k & 1) { fma2(b01, w.x, hv.x); fma2(b23, w.y, hv.y); }
                else       { fma2(a01, w.x, hv.x); fma2(a23, w.y, hv.y); }
            }
            const ulonglong2* x2 = (const ulonglong2*)s_x;
            #pragma unroll
            for (int k = 0; k < 9; k++) {
                ulonglong2 w = __ldg(g_WihT + (k << 9) + r);   // coalesced
                ulonglong2 xv = x2[k];                          // broadcast
                if (k & 1) { fma2(b01, w.x, xv.x); fma2(b23, w.y, xv.y); }
                else       { fma2(a01, w.x, xv.x); fma2(a23, w.y, xv.y); }
            }
            float2 fa = unpack2(a01), fb = unpack2(a23);
            float2 fc = unpack2(b01), fd = unpack2(b23);
            s_g[r] = ((fa.x + fa.y) + (fb.x + fb.y))
                   + ((fc.x + fc.y) + (fd.x + fd.y)) + s_bsum[r];
        }
        __syncthreads();

        // ---- elementwise LSTM update ----
        if (tid < 128) {
            float ig = sigmoidf_(s_g[tid]);
            float fg = sigmoidf_(s_g[128 + tid]);
            float gg = tanhf(s_g[256 + tid]);
            float og = sigmoidf_(s_g[384 + tid]);
            float c = fg * s_c[tid] + ig * gg;
            s_c[tid] = c;
            s_h[tid] = og * tanhf(c);
        }
        __syncthreads();

        // ---- projector logits: 27 outputs x 16 threads ----
        // ALL threads execute the shuffles (clamped index) to keep full-warp
        // participation in __shfl_down_sync.
        {
            int grp = tid >> 4, l = tid & 15;
            int grpc = grp < 27 ? grp : 26;
            const float4* wr = (const float4*)(s_wp + grpc * 132) + l * 2;
            const float4* h4 = (const float4*)s_h + l * 2;
            float4 w0 = wr[0], w1 = wr[1];
            float4 v0 = h4[0], v1 = h4[1];
            float p = w0.x * v0.x + w0.y * v0.y + w0.z * v0.z + w0.w * v0.w
                    + w1.x * v1.x + w1.y * v1.y + w1.z * v1.z + w1.w * v1.w;
            p += __shfl_down_sync(0xffffffffu, p, 8, 16);
            p += __shfl_down_sync(0xffffffffu, p, 4, 16);
            p += __shfl_down_sync(0xffffffffu, p, 2, 16);
            p += __shfl_down_sync(0xffffffffu, p, 1, 16);
            if (l == 0 && grp < 27) s_log[grp] = p + __ldg(bp + grp);
        }
        __syncthreads();
        if (tid < 9) {
            float l0 = s_log[tid * 3], l1 = s_log[tid * 3 + 1], l2 = s_log[tid * 3 + 2];
            float m = fmaxf(l0, fmaxf(l1, l2));
            float e0 = expf(l0 - m), e1 = expf(l1 - m), e2 = expf(l2 - m);
            float inv = 1.0f / (e0 + e1 + e2);
            s_amps[tid * 3 + 0] = sqrtf(e0 * inv);
            s_amps[tid * 3 + 1] = sqrtf(e1 * inv);
            s_amps[tid * 3 + 2] = sqrtf(e2 * inv);
        }
        __syncthreads();

        // ---- 9 collapses, psi in registers, unnormalized with deferred norms ----
        {
            float2 v = s_psi0[tid];
            float nrm[9];
            #pragma unroll
            for (int q = 0; q < 9; q++) {
                float a1 = s_amps[q * 3], a2 = s_amps[q * 3 + 1], a3 = s_amps[q * 3 + 2];
                float an  = sqrtf(a1 * a1 + a2 * a2 + a3 * a3);
                float apn = a3 + an;
                float inv2 = 1.0f / (2.0f * an * apn);
                float t00 = apn * apn * inv2;
                float t11 = (a1 * a1 + a2 * a2) * inv2;
                float cr  = apn * a1 * inv2;
                float ci  = apn * a2 * inv2;
                const int p = 8 - q;
                const int d = 1 << p;
                float2 w;
                if (p >= 5) {
                    float2* buf = s_exch[q & 1];
                    buf[tid] = v;
                    __syncthreads();
                    w = buf[tid ^ d];
                } else {
                    w.x = __shfl_xor_sync(0xffffffffu, v.x, d);
                    w.y = __shfl_xor_sync(0xffffffffu, v.y, d);
                }
                bool hi = (tid & d) != 0;
                float td = hi ? t11 : t00;
                float sg = hi ? -ci : ci;
                float2 nv;
                nv.x = td * v.x + cr * w.x + sg * w.y;
                nv.y = td * v.y + cr * w.y - sg * w.x;
                v = nv;
                nrm[q] = v.x * v.x + v.y * v.y;
            }
            // batched reduction of 9 norms
            #pragma unroll
            for (int q = 0; q < 9; q++) {
                float val = nrm[q];
                #pragma unroll
                for (int off = 16; off; off >>= 1)
                    val += __shfl_xor_sync(0xffffffffu, val, off);
                if (lane == 0) s_red[wid * 12 + q] = val;
            }
            __syncthreads();
            if (tid < 9) {
                float ssum = 0.0f;
                #pragma unroll
                for (int w = 0; w < 16; w++) ssum += s_red[w * 12 + tid];
                s_norm[tid] = ssum;
            }
            __syncthreads();
        }

        // ---- build next input x = [snap(9), amps(27)] ----
        // psi0 is UNNORMALIZED: s_0 = 2*||P0 psi0||^2 - ||psi0||^2.
        // For q >= 1 the chain is normalized: s_q = 2*nrm[q]/nrm[q-1] - 1.
        if (tid < 9) {
            float sq;
            if (tid == 0) sq = 2.0f * s_norm[0] - s_nn0;
            else          sq = 2.0f * s_norm[tid] / s_norm[tid - 1] - 1.0f;
            s_x[tid] = sq;
        } else if (tid < 36) {
            s_x[tid] = s_amps[tid - 9];
        }
        if (t == S - 2 && bv_out != nullptr && tid < 27)
            bv_out[b * 27 + tid] = s_amps[tid];
        __syncthreads();
    }
}

// ---------------------------------------------------------------------------
// Kernel 2: partial Kronecker products per (b, t)
// ---------------------------------------------------------------------------
__global__ void __launch_bounds__(256) k_kron()
{
    int bi = blockIdx.x;            // 0 .. S*B-1
    int b = bi >> 4;
    int t = bi & 15;
    __shared__ float2 s_m[NQ * 4];
    int tid = threadIdx.x;
    if (tid < NQ * 4) s_m[tid] = g_rhoq[(t * B + b) * NQ * 4 + tid];
    __syncthreads();

    // A: qubits 0..3 -> 16x16
    {
        int r = tid >> 4, c = tid & 15;
        float2 v = s_m[0 * 4 + ((r >> 3) & 1) * 2 + ((c >> 3) & 1)];
        #pragma unroll
        for (int q = 1; q < 4; q++) {
            float2 m = s_m[q * 4 + ((r >> (3 - q)) & 1) * 2 + ((c >> (3 - q)) & 1)];
            v = cmul(v, m);
        }
        g_A[(b * S + t) * 256 + tid] = v;
    }
    // B: qubits 4..8 -> 32x32 (4 elems per thread)
    #pragma unroll
    for (int j = 0; j < 4; j++) {
        int lp = tid + j * 256;
        int r = lp >> 5, c = lp & 31;
        float2 v = s_m[4 * 4 + ((r >> 4) & 1) * 2 + ((c >> 4) & 1)];
        #pragma unroll
        for (int q = 5; q < 9; q++) {
            float2 m = s_m[q * 4 + ((r >> (8 - q)) & 1) * 2 + ((c >> (8 - q)) & 1)];
            v = cmul(v, m);
        }
        g_Bm[(b * S + t) * 1024 + lp] = v;
    }
}

// ---------------------------------------------------------------------------
// Kernel 3: acc[b][hp][lp] = (1/S) * sum_t A_t[hp] * B_t[lp], scatter to out
// out layout: [B][2][512][512]  (real plane, imag plane)
// ---------------------------------------------------------------------------
__global__ void __launch_bounds__(256) k_acc(float* __restrict__ out)
{
    int b = blockIdx.z;
    int hpBase = blockIdx.x * 16;
    int tx = threadIdx.x;                 // 0..31 -> lo_c
    int ty = threadIdx.y;                 // 0..7
    int lo_r = blockIdx.y * 8 + ty;
    int lp = lo_r * 32 + tx;
    __shared__ float2 A_s[S][16];
    int tid = ty * 32 + tx;
    {
        int t = tid >> 4, j = tid & 15;
        A_s[t][j] = g_A[(b * S + t) * 256 + hpBase + j];
    }
    __syncthreads();

    float2 acc[16];
    #pragma unroll
    for (int j = 0; j < 16; j++) acc[j] = make_float2(0.0f, 0.0f);

    #pragma unroll
    for (int t = 0; t < S; t++) {
        float2 bv = g_Bm[(b * S + t) * 1024 + lp];
        #pragma unroll
        for (int j = 0; j < 16; j++) {
            float2 a = A_s[t][j];
            acc[j].x += a.x * bv.x - a.y * bv.y;
            acc[j].y += a.x * bv.y + a.y * bv.x;
        }
    }

    const float sc = 1.0f / (float)S;
    float* outr = out + (size_t)b * 2 * D * D;
    float* outi = outr + D * D;
    #pragma unroll
    for (int j = 0; j < 16; j++) {
        int hp = hpBase + j;
        int row = (hp >> 4) * 32 + lo_r;
        int col = (hp & 15) * 32 + tx;
        outr[row * D + col] = acc[j].x * sc;
        outi[row * D + col] = acc[j].y * sc;
    }
}

// ---------------------------------------------------------------------------
extern "C" void kernel_launch(void* const* d_in, const int* in_sizes, int n_in,
                              void* d_out, int out_size)
{
    const float* snapshot = (const float*)d_in[0];
    const float* bcv      = (const float*)d_in[1];
    const float* rho      = (const float*)d_in[2];
    const float* h0       = (const float*)d_in[3];
    const float* c0       = (const float*)d_in[4];
    const float* Wih      = (const float*)d_in[5];
    const float* Whh      = (const float*)d_in[6];
    const float* bih      = (const float*)d_in[7];
    const float* bhh      = (const float*)d_in[8];
    const float* Wp       = (const float*)d_in[9];
    const float* bp       = (const float*)d_in[10];

    float* out = (float*)d_out;
    const int main_elems = 2 * B * D * D;
    const int bv_elems = B * NQ * KK;
    float* bv_out = (out_size >= main_elems + bv_elems) ? (out + main_elems) : nullptr;

    k_transpose<<<82, 256>>>(Whh, Wih);
    k_seq<<<B, NTH>>>(snapshot, bcv, rho, h0, c0, bih, bhh, Wp, bp, bv_out);
    k_kron<<<S * B, 256>>>();
    dim3 g3(16, 4, B);
    k_acc<<<g3, dim3(32, 8)>>>(out);
}